// round 1
// baseline (speedup 1.0000x reference)
#include <cuda_runtime.h>

// SpikeLoss: loss = 0.5 * sum( (outputs - psp(target))^2 )
// psp: syn_t = syn_{t-1}*(1-1/tau_s) + x_t ; y_t = syn_t / tau_s ; tau_s = 5
// Shapes: [B=32, C=256, H=4, W=4, T=100], T contiguous.
// One thread per (b,c,h,w) row: scan 100 contiguous floats via 25 float4 loads.

#define T_STEPS 100
#define VEC_PER_ROW (T_STEPS / 4)   // 25
#define TAU_S 5.0f
#define DECAY (1.0f - 1.0f / TAU_S) // 0.8
#define INV_TAU (1.0f / TAU_S)      // 0.2

#define THREADS 256
#define MAX_BLOCKS 1024

__device__ float g_partials[MAX_BLOCKS];

__global__ void __launch_bounds__(THREADS)
spike_loss_main(const float* __restrict__ outputs,
                const float* __restrict__ target,
                int n_rows)
{
    int row = blockIdx.x * blockDim.x + threadIdx.x;
    float acc = 0.0f;

    if (row < n_rows) {
        const float4* __restrict__ o4 =
            reinterpret_cast<const float4*>(outputs + (size_t)row * T_STEPS);
        const float4* __restrict__ t4 =
            reinterpret_cast<const float4*>(target + (size_t)row * T_STEPS);

        float syn = 0.0f;
        #pragma unroll
        for (int i = 0; i < VEC_PER_ROW; i++) {
            float4 t = t4[i];
            float4 o = o4[i];

            syn = syn * DECAY + t.x;
            float d0 = o.x - syn * INV_TAU;
            acc = fmaf(d0, d0, acc);

            syn = syn * DECAY + t.y;
            float d1 = o.y - syn * INV_TAU;
            acc = fmaf(d1, d1, acc);

            syn = syn * DECAY + t.z;
            float d2 = o.z - syn * INV_TAU;
            acc = fmaf(d2, d2, acc);

            syn = syn * DECAY + t.w;
            float d3 = o.w - syn * INV_TAU;
            acc = fmaf(d3, d3, acc);
        }
    }

    // Warp reduce
    #pragma unroll
    for (int off = 16; off > 0; off >>= 1)
        acc += __shfl_down_sync(0xFFFFFFFFu, acc, off);

    __shared__ float smem[THREADS / 32];
    int lane = threadIdx.x & 31;
    int wid  = threadIdx.x >> 5;
    if (lane == 0) smem[wid] = acc;
    __syncthreads();

    if (wid == 0) {
        acc = (lane < THREADS / 32) ? smem[lane] : 0.0f;
        #pragma unroll
        for (int off = 4; off > 0; off >>= 1)
            acc += __shfl_down_sync(0xFFFFFFFFu, acc, off);
        if (lane == 0)
            g_partials[blockIdx.x] = acc;
    }
}

__global__ void __launch_bounds__(MAX_BLOCKS)
spike_loss_reduce(float* __restrict__ out, int n_blocks)
{
    // Single block, deterministic tree reduction of per-CTA partials.
    float v = (threadIdx.x < n_blocks) ? g_partials[threadIdx.x] : 0.0f;

    #pragma unroll
    for (int off = 16; off > 0; off >>= 1)
        v += __shfl_down_sync(0xFFFFFFFFu, v, off);

    __shared__ float smem[MAX_BLOCKS / 32];
    int lane = threadIdx.x & 31;
    int wid  = threadIdx.x >> 5;
    if (lane == 0) smem[wid] = v;
    __syncthreads();

    if (wid == 0) {
        v = (lane < MAX_BLOCKS / 32) ? smem[lane] : 0.0f;
        #pragma unroll
        for (int off = 16; off > 0; off >>= 1)
            v += __shfl_down_sync(0xFFFFFFFFu, v, off);
        if (lane == 0)
            out[0] = 0.5f * v;
    }
}

extern "C" void kernel_launch(void* const* d_in, const int* in_sizes, int n_in,
                              void* d_out, int out_size)
{
    const float* outputs = (const float*)d_in[0];
    const float* target  = (const float*)d_in[1];
    float* out = (float*)d_out;

    int n_elems = in_sizes[0];
    int n_rows  = n_elems / T_STEPS;              // 131072
    int blocks  = (n_rows + THREADS - 1) / THREADS; // 512

    spike_loss_main<<<blocks, THREADS>>>(outputs, target, n_rows);
    spike_loss_reduce<<<1, MAX_BLOCKS>>>(out, blocks);
}

// round 2
// speedup vs baseline: 1.0048x; 1.0048x over previous
#include <cuda_runtime.h>

// SpikeLoss: loss = 0.5 * sum( (outputs - psp(target))^2 )
// psp: syn_t = syn_{t-1}*0.8 + x_t ; y_t = syn_t * 0.2
// Shapes: [32,256,4,4,100], T=100 contiguous. n_rows = 131072.
//
// Strategy: block = 128 threads = 128 rows. Time split into 5 tiles of 20.
// Coalesced float4 global loads stage each tile into smem (pitch 21,
// conflict-free); each thread then scans its own row out of smem.
// Single kernel: per-block partials + threadfence last-block-done final
// reduce (fixed summation order -> deterministic).

#define T_STEPS   100
#define DECAY     0.8f
#define INV_TAU   0.2f

#define THREADS   128
#define ROWS_PB   128
#define TILE_T    20
#define PITCH     21                       // TILE_T+1, odd -> conflict-free
#define N_TILES   (T_STEPS / TILE_T)       // 5
#define F4_TILE   (TILE_T / 4)             // 5 float4 per row per tile
#define F4_ROW    (T_STEPS / 4)            // 25 float4 per row
#define MAX_BLOCKS 1024                    // 131072 / 128

__device__ float    g_partials[MAX_BLOCKS];
__device__ unsigned g_count = 0;

__global__ void __launch_bounds__(THREADS)
spike_loss_fused(const float* __restrict__ outputs,
                 const float* __restrict__ target,
                 float* __restrict__ out,
                 int n_blocks)
{
    __shared__ float s_t[ROWS_PB * PITCH];
    __shared__ float s_o[ROWS_PB * PITCH];
    __shared__ float s_warp[THREADS / 32];
    __shared__ int   s_is_last;

    const int tid = threadIdx.x;
    const size_t base4 = (size_t)blockIdx.x * ROWS_PB * F4_ROW;
    const float4* __restrict__ gt = (const float4*)target  + base4;
    const float4* __restrict__ go = (const float4*)outputs + base4;

    float syn = 0.0f, acc = 0.0f;
    const float* __restrict__ rt = s_t + tid * PITCH;
    const float* __restrict__ ro = s_o + tid * PITCH;

    #pragma unroll
    for (int tile = 0; tile < N_TILES; tile++) {
        // ---- Coalesced staged load: 640 float4 per array, 5 per thread ----
        #pragma unroll
        for (int k = 0; k < (ROWS_PB * F4_TILE) / THREADS; k++) {  // 5
            int i  = tid + k * THREADS;
            int r  = i / F4_TILE;
            int c4 = i - r * F4_TILE;
            size_t gidx = (size_t)r * F4_ROW + tile * F4_TILE + c4;

            float4 v = gt[gidx];
            float* d = s_t + r * PITCH + c4 * 4;
            d[0] = v.x; d[1] = v.y; d[2] = v.z; d[3] = v.w;

            float4 w = go[gidx];
            float* e = s_o + r * PITCH + c4 * 4;
            e[0] = w.x; e[1] = w.y; e[2] = w.z; e[3] = w.w;
        }
        __syncthreads();

        // ---- Scan this thread's row tile out of smem (conflict-free) ----
        #pragma unroll
        for (int t = 0; t < TILE_T; t++) {
            syn = syn * DECAY + rt[t];
            float d = ro[t] - syn * INV_TAU;
            acc = fmaf(d, d, acc);
        }
        __syncthreads();   // smem reused next tile
    }

    // ---- Block reduction ----
    #pragma unroll
    for (int off = 16; off > 0; off >>= 1)
        acc += __shfl_down_sync(0xFFFFFFFFu, acc, off);

    int lane = tid & 31, wid = tid >> 5;
    if (lane == 0) s_warp[wid] = acc;
    __syncthreads();
    if (tid == 0) {
        float v = s_warp[0] + s_warp[1] + s_warp[2] + s_warp[3];
        g_partials[blockIdx.x] = v;
        __threadfence();
        unsigned old = atomicAdd(&g_count, 1u);
        s_is_last = (old == (unsigned)(n_blocks - 1));
    }
    __syncthreads();

    // ---- Last block: deterministic final reduce over all partials ----
    if (s_is_last) {
        float v = 0.0f;
        #pragma unroll
        for (int j = 0; j < MAX_BLOCKS / THREADS; j++) {  // 8, fixed order
            int idx = tid + j * THREADS;
            if (idx < n_blocks) v += g_partials[idx];
        }
        #pragma unroll
        for (int off = 16; off > 0; off >>= 1)
            v += __shfl_down_sync(0xFFFFFFFFu, v, off);
        if (lane == 0) s_warp[wid] = v;
        __syncthreads();
        if (tid == 0) {
            out[0] = 0.5f * (s_warp[0] + s_warp[1] + s_warp[2] + s_warp[3]);
            g_count = 0;   // reset for next graph replay
        }
    }
}

extern "C" void kernel_launch(void* const* d_in, const int* in_sizes, int n_in,
                              void* d_out, int out_size)
{
    const float* outputs = (const float*)d_in[0];
    const float* target  = (const float*)d_in[1];
    float* out = (float*)d_out;

    int n_rows  = in_sizes[0] / T_STEPS;        // 131072
    int blocks  = n_rows / ROWS_PB;             // 1024

    spike_loss_fused<<<blocks, THREADS>>>(outputs, target, out, blocks);
}